// round 5
// baseline (speedup 1.0000x reference)
#include <cuda_runtime.h>
#include <cstdint>

#define N_NODES 50000
#define CH 128

// Scratch (device globals -- no allocation allowed)
__device__ __align__(16) float g_agg[(size_t)N_NODES * CH];
__device__ __align__(16) float g_h1[(size_t)N_NODES * CH];
__device__ float g_deg[N_NODES];
__device__ int   g_is64;

// ---------------------------------------------------------------------------
// detect: is the edge buffer int64 or int32?
// If int64 (values < 2^31), all high 32-bit words are zero.
// If int32, odd words are uniform edge values in [0, 50000) -> OR != 0.
// One block, deterministic.
// ---------------------------------------------------------------------------
__global__ void detect_kernel(const unsigned* __restrict__ e) {
    __shared__ unsigned red[256];
    unsigned acc = 0;
    int t = threadIdx.x;
    #pragma unroll
    for (int j = 0; j < 8; j++) {
        int slot = t * 8 + j;          // 0..2047
        acc |= e[slot * 2 + 1];        // odd 32-bit words of first 4096 words
    }
    red[t] = acc;
    __syncthreads();
    for (int s = 128; s > 0; s >>= 1) {
        if (t < s) red[t] |= red[t + s];
        __syncthreads();
    }
    if (t == 0) g_is64 = (red[0] == 0) ? 1 : 0;
}

// ---------------------------------------------------------------------------
// clear: zero g_agg (and optionally g_deg)
// ---------------------------------------------------------------------------
__global__ void clear_kernel(int with_deg) {
    int i = blockIdx.x * blockDim.x + threadIdx.x;
    int total = N_NODES * CH / 4;
    if (i < total) ((float4*)g_agg)[i] = make_float4(0.f, 0.f, 0.f, 0.f);
    if (with_deg && i < N_NODES) g_deg[i] = 0.f;
}

// ---------------------------------------------------------------------------
// scatter: one warp per edge. Gather feat[src] (32 x float4), scalar
// atomicAdd (-> REDG.ADD.F32) into g_agg[dst]. Layer 1 also counts degree.
// Edge indices read as int32 or int64 depending on g_is64.
// ---------------------------------------------------------------------------
template <bool FIRST>
__global__ void scatter_kernel(const float* __restrict__ feat_ext,
                               const void* __restrict__ edge_raw,
                               int E) {
    int gw = (blockIdx.x * blockDim.x + threadIdx.x) >> 5;
    int lane = threadIdx.x & 31;
    if (gw >= E) return;

    const float* __restrict__ feat = FIRST ? feat_ext : g_h1;

    int s, d;
    if (g_is64) {
        const long long* e = (const long long*)edge_raw;
        s = (int)e[gw];
        d = (int)e[E + gw];
    } else {
        const int* e = (const int*)edge_raw;
        s = e[gw];
        d = e[E + gw];
    }
    // Defensive: never form a wild address (err 717/700 class traps).
    if ((unsigned)s >= N_NODES || (unsigned)d >= N_NODES) return;

    float4 v = ((const float4*)(feat + (size_t)s * CH))[lane];
    float* out = g_agg + (size_t)d * CH + lane * 4;
    atomicAdd(out + 0, v.x);
    atomicAdd(out + 1, v.y);
    atomicAdd(out + 2, v.z);
    atomicAdd(out + 3, v.w);
    if (FIRST && lane == 0) atomicAdd(g_deg + d, 1.0f);
}

// ---------------------------------------------------------------------------
// combine: h = relu( (agg/deg) @ W_l + b + self @ W_r )
// One K=256 GEMM: k-tiles 0..7 read scaled agg vs W_l, 8..15 self vs W_r.
// BM=128, BN=128, BK=16, 8x8 per thread.
// LAYER==1: self = x (param), out = g_h1. LAYER==2: self = g_h1, out = g_agg.
// ---------------------------------------------------------------------------
#define BM 128
#define BN 128
#define BK 16
#define TM 8
#define TN 8
#define AS_STR 132

template <int LAYER>
__global__ __launch_bounds__(256) void combine_kernel(
    const float* __restrict__ self_ext,
    const float* __restrict__ Wl,
    const float* __restrict__ Wr,
    const float* __restrict__ bias,
    int n)
{
    __shared__ float As[BK][AS_STR];
    __shared__ float Bs[BK][BN];
    __shared__ float sdeg[BM];

    const float* __restrict__ Aagg = g_agg;
    const float* __restrict__ Aself = (LAYER == 1) ? self_ext : g_h1;
    float* __restrict__ out = (LAYER == 1) ? g_h1 : g_agg;

    int block_row = blockIdx.x * BM;
    int t = threadIdx.x;
    int tr = t >> 4;          // 0..15
    int tc = t & 15;          // 0..15

    if (t < BM) {
        int r = block_row + t;
        float dg = (r < n) ? g_deg[r] : 1.0f;
        sdeg[t] = 1.0f / fmaxf(dg, 1.0f);
    }
    __syncthreads();

    float acc[TM][TN] = {};

    #pragma unroll 1
    for (int kt = 0; kt < 16; kt++) {
        const float* Asrc = (kt < 8) ? Aagg : Aself;
        const float* Bsrc = (kt < 8) ? Wl : Wr;
        bool scale = (kt < 8);
        int kofs = (kt & 7) * BK;

        // A tile: 128 rows x 16 cols (2 float4 per thread), stored transposed
        #pragma unroll
        for (int i = 0; i < 2; i++) {
            int slot = t + i * 256;        // 0..511
            int row = slot >> 2;
            int seg = slot & 3;
            int grow = block_row + row;
            float4 v = make_float4(0.f, 0.f, 0.f, 0.f);
            if (grow < n)
                v = *(const float4*)(Asrc + (size_t)grow * CH + kofs + seg * 4);
            if (scale) {
                float sc = sdeg[row];
                v.x *= sc; v.y *= sc; v.z *= sc; v.w *= sc;
            }
            As[seg * 4 + 0][row] = v.x;
            As[seg * 4 + 1][row] = v.y;
            As[seg * 4 + 2][row] = v.z;
            As[seg * 4 + 3][row] = v.w;
        }
        // B tile: 16 rows x 128 cols (2 float4 per thread)
        #pragma unroll
        for (int i = 0; i < 2; i++) {
            int slot = t + i * 256;        // 0..511
            int k = slot >> 5;
            int cseg = slot & 31;
            *(float4*)&Bs[k][cseg * 4] =
                *(const float4*)(Bsrc + (size_t)(kofs + k) * CH + cseg * 4);
        }
        __syncthreads();

        #pragma unroll
        for (int k = 0; k < BK; k++) {
            float4 a0 = *(float4*)&As[k][tr * TM];
            float4 a1 = *(float4*)&As[k][tr * TM + 4];
            float4 b0 = *(float4*)&Bs[k][tc * TN];
            float4 b1 = *(float4*)&Bs[k][tc * TN + 4];
            float ra[TM] = {a0.x, a0.y, a0.z, a0.w, a1.x, a1.y, a1.z, a1.w};
            float rb[TN] = {b0.x, b0.y, b0.z, b0.w, b1.x, b1.y, b1.z, b1.w};
            #pragma unroll
            for (int i = 0; i < TM; i++)
                #pragma unroll
                for (int j = 0; j < TN; j++)
                    acc[i][j] += ra[i] * rb[j];
        }
        __syncthreads();
    }

    float4 bv0 = *(const float4*)&bias[tc * TN];
    float4 bv1 = *(const float4*)&bias[tc * TN + 4];
    float bvec[TN] = {bv0.x, bv0.y, bv0.z, bv0.w, bv1.x, bv1.y, bv1.z, bv1.w};

    #pragma unroll
    for (int i = 0; i < TM; i++) {
        int grow = block_row + tr * TM + i;
        if (grow < n) {
            float4 o0, o1;
            o0.x = fmaxf(acc[i][0] + bvec[0], 0.f);
            o0.y = fmaxf(acc[i][1] + bvec[1], 0.f);
            o0.z = fmaxf(acc[i][2] + bvec[2], 0.f);
            o0.w = fmaxf(acc[i][3] + bvec[3], 0.f);
            o1.x = fmaxf(acc[i][4] + bvec[4], 0.f);
            o1.y = fmaxf(acc[i][5] + bvec[5], 0.f);
            o1.z = fmaxf(acc[i][6] + bvec[6], 0.f);
            o1.w = fmaxf(acc[i][7] + bvec[7], 0.f);
            *(float4*)&out[(size_t)grow * CH + tc * TN] = o0;
            *(float4*)&out[(size_t)grow * CH + tc * TN + 4] = o1;
        }
    }
}

// ---------------------------------------------------------------------------
// decoder: out = alpha * (h2 @ Wd + bd) + (1-alpha) * x   (h2 lives in g_agg)
// ---------------------------------------------------------------------------
__global__ __launch_bounds__(256) void decoder_kernel(
    const float* __restrict__ Wd,
    const float* __restrict__ bd,
    const float* __restrict__ xres,
    const float* __restrict__ alpha_p,
    float* __restrict__ out,
    int n)
{
    __shared__ float As[BK][AS_STR];
    __shared__ float Bs[BK][BN];

    const float* __restrict__ A = g_agg;  // h2

    int block_row = blockIdx.x * BM;
    int t = threadIdx.x;
    int tr = t >> 4;
    int tc = t & 15;

    float acc[TM][TN] = {};

    #pragma unroll 1
    for (int kt = 0; kt < 8; kt++) {
        int kofs = kt * BK;
        #pragma unroll
        for (int i = 0; i < 2; i++) {
            int slot = t + i * 256;
            int row = slot >> 2;
            int seg = slot & 3;
            int grow = block_row + row;
            float4 v = make_float4(0.f, 0.f, 0.f, 0.f);
            if (grow < n)
                v = *(const float4*)(A + (size_t)grow * CH + kofs + seg * 4);
            As[seg * 4 + 0][row] = v.x;
            As[seg * 4 + 1][row] = v.y;
            As[seg * 4 + 2][row] = v.z;
            As[seg * 4 + 3][row] = v.w;
        }
        #pragma unroll
        for (int i = 0; i < 2; i++) {
            int slot = t + i * 256;
            int k = slot >> 5;
            int cseg = slot & 31;
            *(float4*)&Bs[k][cseg * 4] =
                *(const float4*)(Wd + (size_t)(kofs + k) * CH + cseg * 4);
        }
        __syncthreads();

        #pragma unroll
        for (int k = 0; k < BK; k++) {
            float4 a0 = *(float4*)&As[k][tr * TM];
            float4 a1 = *(float4*)&As[k][tr * TM + 4];
            float4 b0 = *(float4*)&Bs[k][tc * TN];
            float4 b1 = *(float4*)&Bs[k][tc * TN + 4];
            float ra[TM] = {a0.x, a0.y, a0.z, a0.w, a1.x, a1.y, a1.z, a1.w};
            float rb[TN] = {b0.x, b0.y, b0.z, b0.w, b1.x, b1.y, b1.z, b1.w};
            #pragma unroll
            for (int i = 0; i < TM; i++)
                #pragma unroll
                for (int j = 0; j < TN; j++)
                    acc[i][j] += ra[i] * rb[j];
        }
        __syncthreads();
    }

    float alpha = *alpha_p;
    float one_m = 1.0f - alpha;

    float4 bv0 = *(const float4*)&bd[tc * TN];
    float4 bv1 = *(const float4*)&bd[tc * TN + 4];
    float bvec[TN] = {bv0.x, bv0.y, bv0.z, bv0.w, bv1.x, bv1.y, bv1.z, bv1.w};

    #pragma unroll
    for (int i = 0; i < TM; i++) {
        int grow = block_row + tr * TM + i;
        if (grow < n) {
            float4 x0 = *(const float4*)&xres[(size_t)grow * CH + tc * TN];
            float4 x1 = *(const float4*)&xres[(size_t)grow * CH + tc * TN + 4];
            float xv[TN] = {x0.x, x0.y, x0.z, x0.w, x1.x, x1.y, x1.z, x1.w};
            float4 o0, o1;
            o0.x = alpha * (acc[i][0] + bvec[0]) + one_m * xv[0];
            o0.y = alpha * (acc[i][1] + bvec[1]) + one_m * xv[1];
            o0.z = alpha * (acc[i][2] + bvec[2]) + one_m * xv[2];
            o0.w = alpha * (acc[i][3] + bvec[3]) + one_m * xv[3];
            o1.x = alpha * (acc[i][4] + bvec[4]) + one_m * xv[4];
            o1.y = alpha * (acc[i][5] + bvec[5]) + one_m * xv[5];
            o1.z = alpha * (acc[i][6] + bvec[6]) + one_m * xv[6];
            o1.w = alpha * (acc[i][7] + bvec[7]) + one_m * xv[7];
            *(float4*)&out[(size_t)grow * CH + tc * TN] = o0;
            *(float4*)&out[(size_t)grow * CH + tc * TN + 4] = o1;
        }
    }
}

// ---------------------------------------------------------------------------
extern "C" void kernel_launch(void* const* d_in, const int* in_sizes, int n_in,
                              void* d_out, int out_size) {
    const float* x     = (const float*)d_in[0];
    const void*  edge  = d_in[1];
    const float* W1_l  = (const float*)d_in[2];
    const float* b1    = (const float*)d_in[3];
    const float* W1_r  = (const float*)d_in[4];
    const float* W2_l  = (const float*)d_in[5];
    const float* b2    = (const float*)d_in[6];
    const float* W2_r  = (const float*)d_in[7];
    const float* Wd    = (const float*)d_in[8];
    const float* bd    = (const float*)d_in[9];
    const float* alpha = (const float*)d_in[10];
    float* out = (float*)d_out;

    int n = in_sizes[0] / CH;            // 50000
    int E = in_sizes[1] / 2;             // 640000 (element count, dtype-agnostic)

    int clear_blocks = (N_NODES * CH / 4 + 255) / 256;
    int scat_blocks  = (E + 7) / 8;      // 8 warps/block, 1 warp/edge
    int gemm_blocks  = (n + BM - 1) / BM;

    // Edge dtype detection (int32 vs int64)
    detect_kernel<<<1, 256>>>((const unsigned*)edge);

    // Layer 1
    clear_kernel<<<clear_blocks, 256>>>(1);
    scatter_kernel<true><<<scat_blocks, 256>>>(x, edge, E);
    combine_kernel<1><<<gemm_blocks, 256>>>(x, W1_l, W1_r, b1, n);

    // Layer 2
    clear_kernel<<<clear_blocks, 256>>>(0);
    scatter_kernel<false><<<scat_blocks, 256>>>(nullptr, edge, E);
    combine_kernel<2><<<gemm_blocks, 256>>>(nullptr, W2_l, W2_r, b2, n);

    // Decoder + residual
    decoder_kernel<<<gemm_blocks, 256>>>(Wd, bd, x, alpha, out, n);
}

// round 6
// speedup vs baseline: 1.4374x; 1.4374x over previous
#include <cuda_runtime.h>
#include <cstdint>

#define N_NODES 50000
#define CH 128

// Scratch (device globals -- no allocation allowed)
__device__ __align__(16) float g_agg[(size_t)N_NODES * CH];
__device__ __align__(16) float g_h1[(size_t)N_NODES * CH];
__device__ float g_deg[N_NODES];
__device__ int   g_is64;

// ---------------------------------------------------------------------------
// packed fp32x2 helpers (Blackwell FFMA2 path; ptxas never auto-fuses this)
// ---------------------------------------------------------------------------
__device__ __forceinline__ unsigned long long pack2(float lo, float hi) {
    unsigned long long r;
    asm("mov.b64 %0, {%1, %2};" : "=l"(r) : "f"(lo), "f"(hi));
    return r;
}
__device__ __forceinline__ void unpack2(unsigned long long v, float& lo, float& hi) {
    asm("mov.b64 {%0, %1}, %2;" : "=f"(lo), "=f"(hi) : "l"(v));
}
__device__ __forceinline__ unsigned long long ffma2(unsigned long long a,
                                                    unsigned long long b,
                                                    unsigned long long c) {
    unsigned long long d;
    asm("fma.rn.f32x2 %0, %1, %2, %3;" : "=l"(d) : "l"(a), "l"(b), "l"(c));
    return d;
}

// ---------------------------------------------------------------------------
// detect: is the edge buffer int64 or int32?
// ---------------------------------------------------------------------------
__global__ void detect_kernel(const unsigned* __restrict__ e) {
    __shared__ unsigned red[256];
    unsigned acc = 0;
    int t = threadIdx.x;
    #pragma unroll
    for (int j = 0; j < 8; j++) {
        int slot = t * 8 + j;
        acc |= e[slot * 2 + 1];
    }
    red[t] = acc;
    __syncthreads();
    for (int s = 128; s > 0; s >>= 1) {
        if (t < s) red[t] |= red[t + s];
        __syncthreads();
    }
    if (t == 0) g_is64 = (red[0] == 0) ? 1 : 0;
}

// ---------------------------------------------------------------------------
// clear: zero g_agg (and optionally g_deg)
// ---------------------------------------------------------------------------
__global__ void clear_kernel(int with_deg) {
    int i = blockIdx.x * blockDim.x + threadIdx.x;
    int total = N_NODES * CH / 4;
    if (i < total) ((float4*)g_agg)[i] = make_float4(0.f, 0.f, 0.f, 0.f);
    if (with_deg && i < N_NODES) g_deg[i] = 0.f;
}

// ---------------------------------------------------------------------------
// scatter: one warp per edge. Gather feat[src] (32 x float4), vector RED
// (red.global.add.v4.f32) into g_agg[dst]. Layer 1 also counts degree.
// Indices bounds-clamped so no wild address can ever form.
// ---------------------------------------------------------------------------
template <bool FIRST>
__global__ void scatter_kernel(const float* __restrict__ feat_ext,
                               const void* __restrict__ edge_raw,
                               int E) {
    int gw = (blockIdx.x * blockDim.x + threadIdx.x) >> 5;
    int lane = threadIdx.x & 31;
    if (gw >= E) return;

    const float* __restrict__ feat = FIRST ? feat_ext : g_h1;

    int s, d;
    if (g_is64) {
        const long long* e = (const long long*)edge_raw;
        s = (int)e[gw];
        d = (int)e[E + gw];
    } else {
        const int* e = (const int*)edge_raw;
        s = e[gw];
        d = e[E + gw];
    }
    if ((unsigned)s >= N_NODES || (unsigned)d >= N_NODES) return;

    float4 v = ((const float4*)(feat + (size_t)s * CH))[lane];
    float* out = g_agg + (size_t)d * CH + lane * 4;
    asm volatile("red.global.add.v4.f32 [%0], {%1,%2,%3,%4};"
                 :: "l"(out), "f"(v.x), "f"(v.y), "f"(v.z), "f"(v.w)
                 : "memory");
    if (FIRST && lane == 0) atomicAdd(g_deg + d, 1.0f);
}

// ---------------------------------------------------------------------------
// combine: h = relu( (agg/deg) @ W_l + b + self @ W_r )
// One K=256 GEMM, BM=128, BN=128, BK=16, 8x8 per thread, f32x2 packed FMA.
// Accumulators packed as row pairs: acc2[p][j] = (row 2p, row 2p+1) x col j.
// ---------------------------------------------------------------------------
#define BM 128
#define BN 128
#define BK 16
#define TM 8
#define TN 8
#define AS_STR 132

template <int LAYER>
__global__ __launch_bounds__(256) void combine_kernel(
    const float* __restrict__ self_ext,
    const float* __restrict__ Wl,
    const float* __restrict__ Wr,
    const float* __restrict__ bias,
    int n)
{
    __shared__ float As[BK][AS_STR];
    __shared__ float Bs[BK][BN];
    __shared__ float sdeg[BM];

    const float* __restrict__ Aagg = g_agg;
    const float* __restrict__ Aself = (LAYER == 1) ? self_ext : g_h1;
    float* __restrict__ out = (LAYER == 1) ? g_h1 : g_agg;

    int block_row = blockIdx.x * BM;
    int t = threadIdx.x;
    int tr = t >> 4;          // 0..15
    int tc = t & 15;          // 0..15

    if (t < BM) {
        int r = block_row + t;
        float dg = (r < n) ? g_deg[r] : 1.0f;
        sdeg[t] = 1.0f / fmaxf(dg, 1.0f);
    }
    __syncthreads();

    unsigned long long acc2[4][TN];
    #pragma unroll
    for (int p = 0; p < 4; p++)
        #pragma unroll
        for (int j = 0; j < TN; j++) acc2[p][j] = 0ull;

    #pragma unroll 1
    for (int kt = 0; kt < 16; kt++) {
        const float* Asrc = (kt < 8) ? Aagg : Aself;
        const float* Bsrc = (kt < 8) ? Wl : Wr;
        bool scale = (kt < 8);
        int kofs = (kt & 7) * BK;

        // A tile: 128 rows x 16 cols (2 float4 per thread), stored transposed
        #pragma unroll
        for (int i = 0; i < 2; i++) {
            int slot = t + i * 256;        // 0..511
            int row = slot >> 2;
            int seg = slot & 3;
            int grow = block_row + row;
            float4 v = make_float4(0.f, 0.f, 0.f, 0.f);
            if (grow < n)
                v = *(const float4*)(Asrc + (size_t)grow * CH + kofs + seg * 4);
            if (scale) {
                float sc = sdeg[row];
                v.x *= sc; v.y *= sc; v.z *= sc; v.w *= sc;
            }
            As[seg * 4 + 0][row] = v.x;
            As[seg * 4 + 1][row] = v.y;
            As[seg * 4 + 2][row] = v.z;
            As[seg * 4 + 3][row] = v.w;
        }
        // B tile: 16 rows x 128 cols (2 float4 per thread)
        #pragma unroll
        for (int i = 0; i < 2; i++) {
            int slot = t + i * 256;        // 0..511
            int k = slot >> 5;
            int cseg = slot & 31;
            *(float4*)&Bs[k][cseg * 4] =
                *(const float4*)(Bsrc + (size_t)(kofs + k) * CH + cseg * 4);
        }
        __syncthreads();

        #pragma unroll
        for (int k = 0; k < BK; k++) {
            // 8 consecutive A rows as 4 packed pairs (16B-aligned LDS)
            ulonglong2 a01 = *(ulonglong2*)&As[k][tr * TM];
            ulonglong2 a23 = *(ulonglong2*)&As[k][tr * TM + 4];
            unsigned long long a2[4] = {a01.x, a01.y, a23.x, a23.y};
            float4 b0 = *(float4*)&Bs[k][tc * TN];
            float4 b1 = *(float4*)&Bs[k][tc * TN + 4];
            unsigned long long b2[TN] = {
                pack2(b0.x, b0.x), pack2(b0.y, b0.y),
                pack2(b0.z, b0.z), pack2(b0.w, b0.w),
                pack2(b1.x, b1.x), pack2(b1.y, b1.y),
                pack2(b1.z, b1.z), pack2(b1.w, b1.w)};
            #pragma unroll
            for (int p = 0; p < 4; p++)
                #pragma unroll
                for (int j = 0; j < TN; j++)
                    acc2[p][j] = ffma2(a2[p], b2[j], acc2[p][j]);
        }
        __syncthreads();
    }

    float4 bv0 = *(const float4*)&bias[tc * TN];
    float4 bv1 = *(const float4*)&bias[tc * TN + 4];
    float bvec[TN] = {bv0.x, bv0.y, bv0.z, bv0.w, bv1.x, bv1.y, bv1.z, bv1.w};

    #pragma unroll
    for (int p = 0; p < 4; p++) {
        float o[2][TN];
        #pragma unroll
        for (int j = 0; j < TN; j++) unpack2(acc2[p][j], o[0][j], o[1][j]);
        #pragma unroll
        for (int h = 0; h < 2; h++) {
            int grow = block_row + tr * TM + 2 * p + h;
            if (grow < n) {
                float4 o0, o1;
                o0.x = fmaxf(o[h][0] + bvec[0], 0.f);
                o0.y = fmaxf(o[h][1] + bvec[1], 0.f);
                o0.z = fmaxf(o[h][2] + bvec[2], 0.f);
                o0.w = fmaxf(o[h][3] + bvec[3], 0.f);
                o1.x = fmaxf(o[h][4] + bvec[4], 0.f);
                o1.y = fmaxf(o[h][5] + bvec[5], 0.f);
                o1.z = fmaxf(o[h][6] + bvec[6], 0.f);
                o1.w = fmaxf(o[h][7] + bvec[7], 0.f);
                *(float4*)&out[(size_t)grow * CH + tc * TN] = o0;
                *(float4*)&out[(size_t)grow * CH + tc * TN + 4] = o1;
            }
        }
    }
}

// ---------------------------------------------------------------------------
// decoder: out = alpha * (h2 @ Wd + bd) + (1-alpha) * x   (h2 lives in g_agg)
// ---------------------------------------------------------------------------
__global__ __launch_bounds__(256) void decoder_kernel(
    const float* __restrict__ Wd,
    const float* __restrict__ bd,
    const float* __restrict__ xres,
    const float* __restrict__ alpha_p,
    float* __restrict__ out,
    int n)
{
    __shared__ float As[BK][AS_STR];
    __shared__ float Bs[BK][BN];

    const float* __restrict__ A = g_agg;  // h2

    int block_row = blockIdx.x * BM;
    int t = threadIdx.x;
    int tr = t >> 4;
    int tc = t & 15;

    unsigned long long acc2[4][TN];
    #pragma unroll
    for (int p = 0; p < 4; p++)
        #pragma unroll
        for (int j = 0; j < TN; j++) acc2[p][j] = 0ull;

    #pragma unroll 1
    for (int kt = 0; kt < 8; kt++) {
        int kofs = kt * BK;
        #pragma unroll
        for (int i = 0; i < 2; i++) {
            int slot = t + i * 256;
            int row = slot >> 2;
            int seg = slot & 3;
            int grow = block_row + row;
            float4 v = make_float4(0.f, 0.f, 0.f, 0.f);
            if (grow < n)
                v = *(const float4*)(A + (size_t)grow * CH + kofs + seg * 4);
            As[seg * 4 + 0][row] = v.x;
            As[seg * 4 + 1][row] = v.y;
            As[seg * 4 + 2][row] = v.z;
            As[seg * 4 + 3][row] = v.w;
        }
        #pragma unroll
        for (int i = 0; i < 2; i++) {
            int slot = t + i * 256;
            int k = slot >> 5;
            int cseg = slot & 31;
            *(float4*)&Bs[k][cseg * 4] =
                *(const float4*)(Wd + (size_t)(kofs + k) * CH + cseg * 4);
        }
        __syncthreads();

        #pragma unroll
        for (int k = 0; k < BK; k++) {
            ulonglong2 a01 = *(ulonglong2*)&As[k][tr * TM];
            ulonglong2 a23 = *(ulonglong2*)&As[k][tr * TM + 4];
            unsigned long long a2[4] = {a01.x, a01.y, a23.x, a23.y};
            float4 b0 = *(float4*)&Bs[k][tc * TN];
            float4 b1 = *(float4*)&Bs[k][tc * TN + 4];
            unsigned long long b2[TN] = {
                pack2(b0.x, b0.x), pack2(b0.y, b0.y),
                pack2(b0.z, b0.z), pack2(b0.w, b0.w),
                pack2(b1.x, b1.x), pack2(b1.y, b1.y),
                pack2(b1.z, b1.z), pack2(b1.w, b1.w)};
            #pragma unroll
            for (int p = 0; p < 4; p++)
                #pragma unroll
                for (int j = 0; j < TN; j++)
                    acc2[p][j] = ffma2(a2[p], b2[j], acc2[p][j]);
        }
        __syncthreads();
    }

    float alpha = *alpha_p;
    float one_m = 1.0f - alpha;

    float4 bv0 = *(const float4*)&bd[tc * TN];
    float4 bv1 = *(const float4*)&bd[tc * TN + 4];
    float bvec[TN] = {bv0.x, bv0.y, bv0.z, bv0.w, bv1.x, bv1.y, bv1.z, bv1.w};

    #pragma unroll
    for (int p = 0; p < 4; p++) {
        float o[2][TN];
        #pragma unroll
        for (int j = 0; j < TN; j++) unpack2(acc2[p][j], o[0][j], o[1][j]);
        #pragma unroll
        for (int h = 0; h < 2; h++) {
            int grow = block_row + tr * TM + 2 * p + h;
            if (grow < n) {
                float4 x0 = *(const float4*)&xres[(size_t)grow * CH + tc * TN];
                float4 x1 = *(const float4*)&xres[(size_t)grow * CH + tc * TN + 4];
                float xv[TN] = {x0.x, x0.y, x0.z, x0.w, x1.x, x1.y, x1.z, x1.w};
                float4 o0, o1;
                o0.x = alpha * (o[h][0] + bvec[0]) + one_m * xv[0];
                o0.y = alpha * (o[h][1] + bvec[1]) + one_m * xv[1];
                o0.z = alpha * (o[h][2] + bvec[2]) + one_m * xv[2];
                o0.w = alpha * (o[h][3] + bvec[3]) + one_m * xv[3];
                o1.x = alpha * (o[h][4] + bvec[4]) + one_m * xv[4];
                o1.y = alpha * (o[h][5] + bvec[5]) + one_m * xv[5];
                o1.z = alpha * (o[h][6] + bvec[6]) + one_m * xv[6];
                o1.w = alpha * (o[h][7] + bvec[7]) + one_m * xv[7];
                *(float4*)&out[(size_t)grow * CH + tc * TN] = o0;
                *(float4*)&out[(size_t)grow * CH + tc * TN + 4] = o1;
            }
        }
    }
}

// ---------------------------------------------------------------------------
extern "C" void kernel_launch(void* const* d_in, const int* in_sizes, int n_in,
                              void* d_out, int out_size) {
    const float* x     = (const float*)d_in[0];
    const void*  edge  = d_in[1];
    const float* W1_l  = (const float*)d_in[2];
    const float* b1    = (const float*)d_in[3];
    const float* W1_r  = (const float*)d_in[4];
    const float* W2_l  = (const float*)d_in[5];
    const float* b2    = (const float*)d_in[6];
    const float* W2_r  = (const float*)d_in[7];
    const float* Wd    = (const float*)d_in[8];
    const float* bd    = (const float*)d_in[9];
    const float* alpha = (const float*)d_in[10];
    float* out = (float*)d_out;

    int n = in_sizes[0] / CH;            // 50000
    int E = in_sizes[1] / 2;             // 640000 (element count, dtype-agnostic)

    int clear_blocks = (N_NODES * CH / 4 + 255) / 256;
    int scat_blocks  = (E + 7) / 8;      // 8 warps/block, 1 warp/edge
    int gemm_blocks  = (n + BM - 1) / BM;

    detect_kernel<<<1, 256>>>((const unsigned*)edge);

    // Layer 1
    clear_kernel<<<clear_blocks, 256>>>(1);
    scatter_kernel<true><<<scat_blocks, 256>>>(x, edge, E);
    combine_kernel<1><<<gemm_blocks, 256>>>(x, W1_l, W1_r, b1, n);

    // Layer 2
    clear_kernel<<<clear_blocks, 256>>>(0);
    scatter_kernel<false><<<scat_blocks, 256>>>(nullptr, edge, E);
    combine_kernel<2><<<gemm_blocks, 256>>>(nullptr, W2_l, W2_r, b2, n);

    // Decoder + residual
    decoder_kernel<<<gemm_blocks, 256>>>(Wd, bd, x, alpha, out, n);
}

// round 8
// speedup vs baseline: 2.1712x; 1.5105x over previous
#include <cuda_runtime.h>
#include <cuda_bf16.h>
#include <cstdint>

#define N_NODES 50000
#define CH 128

// Scratch (device globals -- no allocation allowed)
__device__ __align__(16) float g_agg[(size_t)N_NODES * CH];
__device__ __align__(16) float g_h1[(size_t)N_NODES * CH];
__device__ float g_deg[N_NODES];
__device__ int   g_is64;

// ---------------------------------------------------------------------------
// detect: is the edge buffer int64 or int32?
// ---------------------------------------------------------------------------
__global__ void detect_kernel(const unsigned* __restrict__ e) {
    __shared__ unsigned red[256];
    unsigned acc = 0;
    int t = threadIdx.x;
    #pragma unroll
    for (int j = 0; j < 8; j++) acc |= e[(t * 8 + j) * 2 + 1];
    red[t] = acc;
    __syncthreads();
    for (int s = 128; s > 0; s >>= 1) {
        if (t < s) red[t] |= red[t + s];
        __syncthreads();
    }
    if (t == 0) g_is64 = (red[0] == 0) ? 1 : 0;
}

// ---------------------------------------------------------------------------
// clear: zero g_agg (and optionally g_deg)
// ---------------------------------------------------------------------------
__global__ void clear_kernel(int with_deg) {
    int i = blockIdx.x * blockDim.x + threadIdx.x;
    int total = N_NODES * CH / 4;
    if (i < total) ((float4*)g_agg)[i] = make_float4(0.f, 0.f, 0.f, 0.f);
    if (with_deg && i < N_NODES) g_deg[i] = 0.f;
}

// ---------------------------------------------------------------------------
// scatter: one warp per edge, vector RED (proven, ~LTS floor)
// ---------------------------------------------------------------------------
template <bool FIRST>
__global__ void scatter_kernel(const float* __restrict__ feat_ext,
                               const void* __restrict__ edge_raw,
                               int E) {
    int gw = (blockIdx.x * blockDim.x + threadIdx.x) >> 5;
    int lane = threadIdx.x & 31;
    if (gw >= E) return;

    const float* __restrict__ feat = FIRST ? feat_ext : g_h1;

    int s, d;
    if (g_is64) {
        const long long* e = (const long long*)edge_raw;
        s = (int)e[gw];
        d = (int)e[E + gw];
    } else {
        const int* e = (const int*)edge_raw;
        s = e[gw];
        d = e[E + gw];
    }
    if ((unsigned)s >= N_NODES || (unsigned)d >= N_NODES) return;

    float4 v = ((const float4*)(feat + (size_t)s * CH))[lane];
    float* out = g_agg + (size_t)d * CH + lane * 4;
    asm volatile("red.global.add.v4.f32 [%0], {%1,%2,%3,%4};"
                 :: "l"(out), "f"(v.x), "f"(v.y), "f"(v.z), "f"(v.w)
                 : "memory");
    if (FIRST && lane == 0) atomicAdd(g_deg + d, 1.0f);
}

// ---------------------------------------------------------------------------
// GEMM via mma.sync m16n8k16 bf16 (HMMA), bf16x3 error-compensated split:
//   D = Ahi*Bhi + Ahi*Blo + Alo*Bhi   (fp32 accumulate)
// Tile: BM=64 rows/CTA, BN=128 (full width), K chunks of 32.
// 256 threads = 8 warps in a 2(M) x 4(N) grid; warp tile 32x32.
// MODE 1: relu( [agg/deg | x]  @ [W1_l;W1_r] + b1 ) -> g_h1     (K=256)
// MODE 2: relu( [agg/deg | h1] @ [W2_l;W2_r] + b2 ) -> g_agg    (K=256)
// MODE 3: alpha*(agg @ Wd + bd) + (1-alpha)*xres    -> out_ext  (K=128)
// ---------------------------------------------------------------------------
#define BM 64
#define KC 32
#define ASTR 40   // bf16 row stride: 20 words -> conflict-free frag loads

__device__ __forceinline__ void mma_bf16(float* d, const uint32_t* a,
                                         const uint32_t* b) {
    asm volatile(
        "mma.sync.aligned.m16n8k16.row.col.f32.bf16.bf16.f32 "
        "{%0,%1,%2,%3}, {%4,%5,%6,%7}, {%8,%9}, {%0,%1,%2,%3};"
        : "+f"(d[0]), "+f"(d[1]), "+f"(d[2]), "+f"(d[3])
        : "r"(a[0]), "r"(a[1]), "r"(a[2]), "r"(a[3]), "r"(b[0]), "r"(b[1]));
}

__device__ __forceinline__ uint32_t bf2_hi(float x, float y) {
    __nv_bfloat162 h = __floats2bfloat162_rn(x, y);
    return *(uint32_t*)&h;
}

template <int MODE>
__global__ __launch_bounds__(256) void gemm_kernel(
    const float* __restrict__ selfA,   // MODE 1: x
    const float* __restrict__ Wa,      // W_l (or Wd)
    const float* __restrict__ Wb,      // W_r (MODE 1/2)
    const float* __restrict__ bias,
    const float* __restrict__ xres,    // MODE 3
    const float* __restrict__ alpha_p, // MODE 3
    float* __restrict__ out_ext,       // MODE 3
    int n)
{
    __shared__ __nv_bfloat16 Ahi[BM][ASTR];
    __shared__ __nv_bfloat16 Alo[BM][ASTR];
    __shared__ __nv_bfloat16 Bhi[128][ASTR];
    __shared__ __nv_bfloat16 Blo[128][ASTR];
    __shared__ float s_bias[128];
    __shared__ float s_deg[BM];

    int t = threadIdx.x;
    int lane = t & 31;
    int w = t >> 5;
    int wm = w >> 2;          // 0..1  (M)
    int wn = w & 3;           // 0..3  (N)
    int block_row = blockIdx.x * BM;

    if (t < 128) s_bias[t] = bias[t];
    if (t < BM && MODE != 3) {
        int r = block_row + t;
        float dg = (r < n) ? g_deg[r] : 1.0f;
        s_deg[t] = 1.0f / fmaxf(dg, 1.0f);
    }

    float acc[2][4][4];
    #pragma unroll
    for (int mi = 0; mi < 2; mi++)
        #pragma unroll
        for (int nj = 0; nj < 4; nj++)
            #pragma unroll
            for (int q = 0; q < 4; q++) acc[mi][nj][q] = 0.f;

    const int NCH = (MODE == 3) ? 4 : 8;

    #pragma unroll 1
    for (int c = 0; c < NCH; c++) {
        const float* Asrc;
        const float* Bsrc;
        bool scale;
        int kofs;
        if (MODE == 3) { Asrc = g_agg; Bsrc = Wa; scale = false; kofs = c * KC; }
        else {
            scale = (c < 4);
            kofs = (c & 3) * KC;
            Asrc = (c < 4) ? g_agg : ((MODE == 1) ? selfA : g_h1);
            Bsrc = (c < 4) ? Wa : Wb;
        }
        __syncthreads();   // previous chunk's mma reads done before restage

        // ---- stage A: 64 rows x 32 k, fp32 -> bf16 hi/lo ----
        {
            int row = t >> 2;            // 0..63
            int ks = (t & 3) * 8;        // 0,8,16,24
            int grow = block_row + row;
            float4 v0 = make_float4(0.f, 0.f, 0.f, 0.f);
            float4 v1 = v0;
            if (grow < n) {
                const float* p = Asrc + (size_t)grow * CH + kofs + ks;
                v0 = *(const float4*)p;
                v1 = *(const float4*)(p + 4);
            }
            if (MODE != 3 && scale) {
                float sc = s_deg[row];
                v0.x *= sc; v0.y *= sc; v0.z *= sc; v0.w *= sc;
                v1.x *= sc; v1.y *= sc; v1.z *= sc; v1.w *= sc;
            }
            uint4 hi, lo;
            hi.x = bf2_hi(v0.x, v0.y);  hi.y = bf2_hi(v0.z, v0.w);
            hi.z = bf2_hi(v1.x, v1.y);  hi.w = bf2_hi(v1.z, v1.w);
            float2 h0 = __bfloat1622float2(*(__nv_bfloat162*)&hi.x);
            float2 h1 = __bfloat1622float2(*(__nv_bfloat162*)&hi.y);
            float2 h2 = __bfloat1622float2(*(__nv_bfloat162*)&hi.z);
            float2 h3 = __bfloat1622float2(*(__nv_bfloat162*)&hi.w);
            lo.x = bf2_hi(v0.x - h0.x, v0.y - h0.y);
            lo.y = bf2_hi(v0.z - h1.x, v0.w - h1.y);
            lo.z = bf2_hi(v1.x - h2.x, v1.y - h2.y);
            lo.w = bf2_hi(v1.z - h3.x, v1.w - h3.y);
            *(uint4*)&Ahi[row][ks] = hi;
            *(uint4*)&Alo[row][ks] = lo;
        }

        // ---- stage B (transposed): Bs[n][k] = W[kofs+k][n], hi/lo ----
        {
            int nn = t >> 1;             // 0..127
            int ks = (t & 1) * 16;       // 0,16
            uint32_t hw[8], lw[8];
            #pragma unroll
            for (int j = 0; j < 8; j++) {
                float va = Bsrc[(size_t)(kofs + ks + 2 * j) * CH + nn];
                float vb = Bsrc[(size_t)(kofs + ks + 2 * j + 1) * CH + nn];
                hw[j] = bf2_hi(va, vb);
                float2 hf = __bfloat1622float2(*(__nv_bfloat162*)&hw[j]);
                lw[j] = bf2_hi(va - hf.x, vb - hf.y);
            }
            *(uint4*)&Bhi[nn][ks]     = make_uint4(hw[0], hw[1], hw[2], hw[3]);
            *(uint4*)&Bhi[nn][ks + 8] = make_uint4(hw[4], hw[5], hw[6], hw[7]);
            *(uint4*)&Blo[nn][ks]     = make_uint4(lw[0], lw[1], lw[2], lw[3]);
            *(uint4*)&Blo[nn][ks + 8] = make_uint4(lw[4], lw[5], lw[6], lw[7]);
        }
        __syncthreads();

        // ---- mma: 2 k16-steps, 3 passes each ----
        #pragma unroll
        for (int kk = 0; kk < KC; kk += 16) {
            int kw = kk + (lane & 3) * 2;
            int rr = wm * 32 + (lane >> 2);
            uint32_t ah[2][4], al[2][4], bh[4][2], bl[4][2];
            #pragma unroll
            for (int mi = 0; mi < 2; mi++) {
                int r = rr + mi * 16;
                ah[mi][0] = *(uint32_t*)&Ahi[r][kw];
                ah[mi][1] = *(uint32_t*)&Ahi[r + 8][kw];
                ah[mi][2] = *(uint32_t*)&Ahi[r][kw + 8];
                ah[mi][3] = *(uint32_t*)&Ahi[r + 8][kw + 8];
                al[mi][0] = *(uint32_t*)&Alo[r][kw];
                al[mi][1] = *(uint32_t*)&Alo[r + 8][kw];
                al[mi][2] = *(uint32_t*)&Alo[r][kw + 8];
                al[mi][3] = *(uint32_t*)&Alo[r + 8][kw + 8];
            }
            #pragma unroll
            for (int nj = 0; nj < 4; nj++) {
                int cn = wn * 32 + nj * 8 + (lane >> 2);
                bh[nj][0] = *(uint32_t*)&Bhi[cn][kw];
                bh[nj][1] = *(uint32_t*)&Bhi[cn][kw + 8];
                bl[nj][0] = *(uint32_t*)&Blo[cn][kw];
                bl[nj][1] = *(uint32_t*)&Blo[cn][kw + 8];
            }
            #pragma unroll
            for (int mi = 0; mi < 2; mi++)
                #pragma unroll
                for (int nj = 0; nj < 4; nj++) {
                    mma_bf16(acc[mi][nj], ah[mi], bh[nj]);
                    mma_bf16(acc[mi][nj], ah[mi], bl[nj]);
                    mma_bf16(acc[mi][nj], al[mi], bh[nj]);
                }
        }
    }

    // ---- epilogue ----
    float alpha = 0.f, one_m = 0.f;
    if (MODE == 3) { alpha = *alpha_p; one_m = 1.0f - alpha; }
    float* outp = (MODE == 1) ? g_h1 : ((MODE == 2) ? g_agg : out_ext);

    #pragma unroll
    for (int mi = 0; mi < 2; mi++) {
        #pragma unroll
        for (int part = 0; part < 2; part++) {
            int grow = block_row + wm * 32 + mi * 16 + part * 8 + (lane >> 2);
            if (grow < n) {
                #pragma unroll
                for (int nj = 0; nj < 4; nj++) {
                    int gcol = wn * 32 + nj * 8 + (lane & 3) * 2;
                    float v0 = acc[mi][nj][part * 2 + 0] + s_bias[gcol];
                    float v1 = acc[mi][nj][part * 2 + 1] + s_bias[gcol + 1];
                    float2 o;
                    if (MODE == 3) {
                        float2 xv = *(const float2*)(xres + (size_t)grow * CH + gcol);
                        o.x = alpha * v0 + one_m * xv.x;
                        o.y = alpha * v1 + one_m * xv.y;
                    } else {
                        o.x = fmaxf(v0, 0.f);
                        o.y = fmaxf(v1, 0.f);
                    }
                    *(float2*)(outp + (size_t)grow * CH + gcol) = o;
                }
            }
        }
    }
}

// ---------------------------------------------------------------------------
extern "C" void kernel_launch(void* const* d_in, const int* in_sizes, int n_in,
                              void* d_out, int out_size) {
    const float* x     = (const float*)d_in[0];
    const void*  edge  = d_in[1];
    const float* W1_l  = (const float*)d_in[2];
    const float* b1    = (const float*)d_in[3];
    const float* W1_r  = (const float*)d_in[4];
    const float* W2_l  = (const float*)d_in[5];
    const float* b2    = (const float*)d_in[6];
    const float* W2_r  = (const float*)d_in[7];
    const float* Wd    = (const float*)d_in[8];
    const float* bd    = (const float*)d_in[9];
    const float* alpha = (const float*)d_in[10];
    float* out = (float*)d_out;

    int n = in_sizes[0] / CH;            // 50000
    int E = in_sizes[1] / 2;             // 640000

    int clear_blocks = (N_NODES * CH / 4 + 255) / 256;
    int scat_blocks  = (E + 7) / 8;
    int gemm_blocks  = (n + BM - 1) / BM;   // 782

    detect_kernel<<<1, 256>>>((const unsigned*)edge);

    // Layer 1
    clear_kernel<<<clear_blocks, 256>>>(1);
    scatter_kernel<true><<<scat_blocks, 256>>>(x, edge, E);
    gemm_kernel<1><<<gemm_blocks, 256>>>(x, W1_l, W1_r, b1,
                                         nullptr, nullptr, nullptr, n);
    // Layer 2
    clear_kernel<<<clear_blocks, 256>>>(0);
    scatter_kernel<false><<<scat_blocks, 256>>>(nullptr, edge, E);
    gemm_kernel<2><<<gemm_blocks, 256>>>(nullptr, W2_l, W2_r, b2,
                                         nullptr, nullptr, nullptr, n);
    // Decoder + residual
    gemm_kernel<3><<<gemm_blocks, 256>>>(nullptr, Wd, nullptr, bd,
                                         x, alpha, out, n);
}